// round 16
// baseline (speedup 1.0000x reference)
#include <cuda_runtime.h>
#include <cuda_fp16.h>
#include <math.h>
#include <stdint.h>

#define NNODE  100000
#define EMAX   3200000
#define EPAD   4000064              // E + 8*N headroom (padded CSR)
#define HDIM   128
#define CDIM   10
#define H10P   16                   // padded h10 row (halves) = 32 B
#define NGRAPH 512

// ---------------- scratch (device globals; no allocation allowed) -------
__device__ __half g_hs16 [(NNODE + 1) * HDIM]; // +1 dummy zero row
__device__ __half g_feat16[NNODE * HDIM];
__device__ uint2  g_bfrag[3 * 8 * 16 * 32];    // W in mma B-fragment layout
__device__ __half g_h10 [(NNODE + 1) * H10P];  // fp16, sector-aligned rows
__device__ int   g_deg [NNODE];
__device__ float g_dinv[NNODE];
__device__ int   g_rowptr[NNODE + 1];
__device__ int   g_cursor[NNODE];
__device__ int   g_col [EPAD];
__device__ int   g_bsum[128];
__device__ int   g_boff[128];
__device__ float g_sums[NGRAPH * CDIM];
__device__ float g_cnts[NGRAPH];

__device__ __forceinline__ int clampi(int v, int n) {
    return (v < 0) ? 0 : ((v >= n) ? n - 1 : v);
}

__device__ __forceinline__ uint32_t smem_u32(const void* p) {
    uint32_t a;
    asm("{ .reg .u64 t; cvta.to.shared.u64 t, %1; cvt.u32.u64 %0, t; }"
        : "=r"(a) : "l"(p));
    return a;
}

// ---------------- init ---------------------------------------------------
__global__ void k_zero(int n) {
    int i = blockIdx.x * blockDim.x + threadIdx.x;
    if (i < n) g_deg[i] = 0;
    if (i < NGRAPH * CDIM) g_sums[i] = 0.0f;
    if (i < NGRAPH) g_cnts[i] = 0.0f;
    if (i < HDIM / 2) ((unsigned int*)(g_hs16 + NNODE * HDIM))[i] = 0u;
    if (i < H10P / 2) ((unsigned int*)(g_h10 + NNODE * H10P))[i] = 0u;
}

__global__ void k_count(const int* __restrict__ ei,
                        const int* __restrict__ batch, int E, int n) {
    int e = blockIdx.x * blockDim.x + threadIdx.x;
    if (e < E) atomicAdd(&g_deg[clampi(ei[E + e], n)], 1);
    if (e < n) atomicAdd(&g_cnts[clampi(batch[e], NGRAPH)], 1.0f);
}

// fused: dinv + W fragment packing
__global__ void k_dinv_prepW(const float* __restrict__ W0,
                             const float* __restrict__ W1,
                             const float* __restrict__ W2, int n) {
    int idx = blockIdx.x * blockDim.x + threadIdx.x;
    if (idx < n) g_dinv[idx] = rsqrtf((float)(g_deg[idx] + 1));
    if (idx < 3 * 8 * 16 * 32) {
        int lane = idx & 31;
        int f = (idx >> 5) & 15;
        int s = (idx >> 9) & 7;
        int l = idx >> 12;
        const float* W = (l == 0) ? W0 : (l == 1) ? W1 : W2;
        int kb = s * 16 + 2 * (lane & 3);
        int nn = f * 8 + (lane >> 2);
        __half2 h0 = __floats2half2_rn(W[kb * HDIM + nn], W[(kb + 1) * HDIM + nn]);
        __half2 h1 = __floats2half2_rn(W[(kb + 8) * HDIM + nn], W[(kb + 9) * HDIM + nn]);
        uint2 v;
        v.x = *(unsigned int*)&h0;
        v.y = *(unsigned int*)&h1;
        g_bfrag[idx] = v;
    }
}

// scans operate on PADDED degrees: pdeg = (deg+7) & ~7
__global__ void k_scan1(int n) {
    __shared__ int s[1024];
    int t = threadIdx.x;
    int i = blockIdx.x * 1024 + t;
    s[t] = (i < n) ? ((g_deg[i] + 7) & ~7) : 0;
    __syncthreads();
    for (int st = 512; st > 0; st >>= 1) {
        if (t < st) s[t] += s[t + st];
        __syncthreads();
    }
    if (t == 0) g_bsum[blockIdx.x] = s[0];
}

__global__ void k_scan2(int nb) {
    __shared__ int s[128];
    int t = threadIdx.x;
    int my = (t < nb) ? g_bsum[t] : 0;
    s[t] = my;
    __syncthreads();
    for (int st = 1; st < 128; st <<= 1) {
        int v = (t >= st) ? s[t - st] : 0;
        __syncthreads();
        s[t] += v;
        __syncthreads();
    }
    g_boff[t] = s[t] - my;
}

__global__ void k_scan3(int n) {
    __shared__ int s[1024];
    int t = threadIdx.x;
    int i = blockIdx.x * 1024 + t;
    int v0 = (i < n) ? ((g_deg[i] + 7) & ~7) : 0;
    s[t] = v0;
    __syncthreads();
    for (int st = 1; st < 1024; st <<= 1) {
        int v = (t >= st) ? s[t - st] : 0;
        __syncthreads();
        s[t] += v;
        __syncthreads();
    }
    if (i < n) {
        int excl = g_boff[blockIdx.x] + s[t] - v0;
        g_rowptr[i] = excl;
        g_cursor[i] = excl;
        if (i == n - 1) g_rowptr[n] = g_boff[blockIdx.x] + s[t];
    }
}

__global__ void k_fill(const int* __restrict__ ei, int E, int n) {
    int e = blockIdx.x * blockDim.x + threadIdx.x;
    if (e < E) {
        int src = clampi(ei[e], n);
        int dst = clampi(ei[E + e], n);
        int p = atomicAdd(&g_cursor[dst], 1);
        g_col[p] = src;
    }
}

// fill padding slots (<=7 per node) with dummy index
__global__ void k_padfill(int n) {
    int i = blockIdx.x * blockDim.x + threadIdx.x;
    if (i >= n) return;
    int p0 = g_rowptr[i] + g_deg[i];
    int p1 = g_rowptr[i + 1];
    for (int p = p0; p < p1; p++) g_col[p] = NNODE;
}

// ---------------- HMMA GEMM (R13 8-warp smem/ldmatrix, N-split) ----------
#define APAD 136
__global__ void __launch_bounds__(256)
k_gemm_mma(const float* __restrict__ xin, int layer, int n, int src) {
    __shared__ __half As[128 * APAD];
    int tid = threadIdx.x;
    int wid = tid >> 5, lane = tid & 31;
    int nh = blockIdx.x & 1;
    int rb = (blockIdx.x >> 1) * 128;

    for (int i = tid; i < 2048; i += 256) {
        int r = i >> 4, j = i & 15;
        int gr = rb + r;
        uint4 v = make_uint4(0u, 0u, 0u, 0u);
        if (gr < n) {
            if (src == 0) {
                const float4* p = (const float4*)(xin + (long long)gr * HDIM + j * 8);
                float4 f0 = p[0], f1 = p[1];
                __half2 h0 = __floats2half2_rn(f0.x, f0.y);
                __half2 h1 = __floats2half2_rn(f0.z, f0.w);
                __half2 h2 = __floats2half2_rn(f1.x, f1.y);
                __half2 h3 = __floats2half2_rn(f1.z, f1.w);
                v.x = *(unsigned int*)&h0; v.y = *(unsigned int*)&h1;
                v.z = *(unsigned int*)&h2; v.w = *(unsigned int*)&h3;
            } else {
                v = *(const uint4*)(g_feat16 + (long long)gr * HDIM + j * 8);
            }
        }
        *(uint4*)&As[r * APAD + j * 8] = v;
    }
    __syncthreads();

    float acc[8][4];
    #pragma unroll
    for (int f = 0; f < 8; f++)
        #pragma unroll
        for (int j = 0; j < 4; j++) acc[f][j] = 0.f;

    const uint2* bf = g_bfrag + (layer * 8) * 16 * 32 + (nh * 8) * 32;
    int wr = wid * 16;
    int g = lane >> 3, rr = lane & 7;
    uint32_t a_base = smem_u32(As) +
        (uint32_t)(((wr + (g & 1) * 8 + rr) * APAD) * 2);

    #pragma unroll
    for (int s = 0; s < 8; s++) {
        uint32_t a0, a1, a2, a3;
        uint32_t addr = a_base + (uint32_t)((s * 16 + (g >> 1) * 8) * 2);
        asm volatile("ldmatrix.sync.aligned.m8n8.x4.shared.b16 {%0,%1,%2,%3}, [%4];"
                     : "=r"(a0), "=r"(a1), "=r"(a2), "=r"(a3) : "r"(addr));
        const uint2* bs = bf + s * 16 * 32 + lane;
        #pragma unroll
        for (int f = 0; f < 8; f++) {
            uint2 b = __ldg(&bs[f * 32]);
            asm volatile(
                "mma.sync.aligned.m16n8k16.row.col.f32.f16.f16.f32 "
                "{%0,%1,%2,%3}, {%4,%5,%6,%7}, {%8,%9}, {%0,%1,%2,%3};"
                : "+f"(acc[f][0]), "+f"(acc[f][1]), "+f"(acc[f][2]), "+f"(acc[f][3])
                : "r"(a0), "r"(a1), "r"(a2), "r"(a3), "r"(b.x), "r"(b.y));
        }
    }

    int r0 = rb + wr + (lane >> 2);
    int r1 = r0 + 8;
    float di0 = (r0 < n) ? g_dinv[r0] : 0.f;
    float di1 = (r1 < n) ? g_dinv[r1] : 0.f;
    #pragma unroll
    for (int f = 0; f < 8; f++) {
        int c = nh * 64 + f * 8 + 2 * (lane & 3);
        if (r0 < n) {
            __half2 h = __floats2half2_rn(acc[f][0] * di0, acc[f][1] * di0);
            *(unsigned int*)(g_hs16 + (long long)r0 * HDIM + c) = *(unsigned int*)&h;
        }
        if (r1 < n) {
            __half2 h = __floats2half2_rn(acc[f][2] * di1, acc[f][3] * di1);
            *(unsigned int*)(g_hs16 + (long long)r1 * HDIM + c) = *(unsigned int*)&h;
        }
    }
}

// ---------------- 128-wide pull aggregation: half-warp split, 16B loads --
// Lane = (half, sub): half=lane>>4 processes even/odd edges; sub indexes the
// 16B chunk of the 256B feature row. Final shfl_xor(16) combines halves.
__global__ void __launch_bounds__(256)
k_agg128(const float* __restrict__ bias, const float* __restrict__ Wout,
         int n, int fin) {
    __shared__ float Wsm[HDIM * CDIM];
    if (fin) {
        for (int i = threadIdx.x; i < HDIM * CDIM; i += 256)
            Wsm[i] = Wout[i];
        __syncthreads();
    }
    int w = (blockIdx.x * 256 + threadIdx.x) >> 5;
    int lane = threadIdx.x & 31;
    if (w >= n) return;
    int half = lane >> 4;                 // 0: even edges, 1: odd edges
    int sub = lane & 15;                  // 16B chunk index
    const uint4* base4 = (const uint4*)g_hs16;   // 16 uint4 per row

    float a[8];
    if (half == 0) {                      // self loop on half 0 only
        uint4 v = base4[w * 16 + sub];
        float2 f0 = __half22float2(*(__half2*)&v.x);
        float2 f1 = __half22float2(*(__half2*)&v.y);
        float2 f2 = __half22float2(*(__half2*)&v.z);
        float2 f3 = __half22float2(*(__half2*)&v.w);
        a[0] = f0.x; a[1] = f0.y; a[2] = f1.x; a[3] = f1.y;
        a[4] = f2.x; a[5] = f2.y; a[6] = f3.x; a[7] = f3.y;
    } else {
        #pragma unroll
        for (int k = 0; k < 8; k++) a[k] = 0.f;
    }

    int e0 = g_rowptr[w], e1 = g_rowptr[w + 1];
    for (int e = e0; e < e1; e += 32) {
        int me = e + lane;
        int ms = (me < e1) ? g_col[me] : NNODE;
        #pragma unroll
        for (int g = 0; g < 32; g += 8) {
            if (e + g >= e1) break;       // groups of 8 always complete
            uint4 b[4];
            #pragma unroll
            for (int j = 0; j < 4; j++) {
                int s = __shfl_sync(0xffffffffu, ms, g + 2 * j + half);
                b[j] = base4[s * 16 + sub];
            }
            #pragma unroll
            for (int j = 0; j < 4; j++) {
                float2 f0 = __half22float2(*(__half2*)&b[j].x);
                float2 f1 = __half22float2(*(__half2*)&b[j].y);
                float2 f2 = __half22float2(*(__half2*)&b[j].z);
                float2 f3 = __half22float2(*(__half2*)&b[j].w);
                a[0] += f0.x; a[1] += f0.y; a[2] += f1.x; a[3] += f1.y;
                a[4] += f2.x; a[5] += f2.y; a[6] += f3.x; a[7] += f3.y;
            }
        }
    }
    // combine halves (both halves end with identical full sums)
    #pragma unroll
    for (int k = 0; k < 8; k++)
        a[k] += __shfl_xor_sync(0xffffffffu, a[k], 16);

    float di = g_dinv[w];
    float4 bv0 = ((const float4*)bias)[sub * 2];
    float4 bv1 = ((const float4*)bias)[sub * 2 + 1];
    float o[8];
    o[0] = fmaxf(fmaf(di, a[0], bv0.x), 0.f);
    o[1] = fmaxf(fmaf(di, a[1], bv0.y), 0.f);
    o[2] = fmaxf(fmaf(di, a[2], bv0.z), 0.f);
    o[3] = fmaxf(fmaf(di, a[3], bv0.w), 0.f);
    o[4] = fmaxf(fmaf(di, a[4], bv1.x), 0.f);
    o[5] = fmaxf(fmaf(di, a[5], bv1.y), 0.f);
    o[6] = fmaxf(fmaf(di, a[6], bv1.z), 0.f);
    o[7] = fmaxf(fmaf(di, a[7], bv1.w), 0.f);

    if (!fin) {
        if (half == 0) {                  // 16 lanes x 16B = full row
            uint4 st;
            __half2 h0 = __floats2half2_rn(o[0], o[1]);
            __half2 h1 = __floats2half2_rn(o[2], o[3]);
            __half2 h2 = __floats2half2_rn(o[4], o[5]);
            __half2 h3 = __floats2half2_rn(o[6], o[7]);
            st.x = *(unsigned int*)&h0; st.y = *(unsigned int*)&h1;
            st.z = *(unsigned int*)&h2; st.w = *(unsigned int*)&h3;
            ((uint4*)g_feat16)[w * 16 + sub] = st;
        }
    } else {
        // fused 128->10 projection; features duplicated across halves -> x0.5
        float p[CDIM];
        #pragma unroll
        for (int c = 0; c < CDIM; c++) p[c] = 0.f;
        #pragma unroll
        for (int j = 0; j < 8; j++) {
            const float* wr = &Wsm[(8 * sub + j) * CDIM];
            #pragma unroll
            for (int c = 0; c < CDIM; c++)
                p[c] = fmaf(o[j], wr[c], p[c]);
        }
        #pragma unroll
        for (int c = 0; c < CDIM; c++) {
            #pragma unroll
            for (int off = 16; off > 0; off >>= 1)
                p[c] += __shfl_xor_sync(0xffffffffu, p[c], off);
        }
        if (lane == 0) {
            __half* dst = &g_h10[w * H10P];
            unsigned int pk[8];
            #pragma unroll
            for (int c = 0; c < 5; c++) {
                __half2 h = __floats2half2_rn(p[2 * c] * di * 0.5f,
                                              p[2 * c + 1] * di * 0.5f);
                pk[c] = *(unsigned int*)&h;
            }
            pk[5] = 0u; pk[6] = 0u; pk[7] = 0u;
            uint4* d4 = (uint4*)dst;
            d4[0] = make_uint4(pk[0], pk[1], pk[2], pk[3]);
            d4[1] = make_uint4(pk[4], pk[5], pk[6], pk[7]);
        }
    }
}

// 10-wide aggregation fused with mean-pool (fp16 h10, padded CSR)
__global__ void __launch_bounds__(256)
k_agg10pool(const float* __restrict__ bias, const int* __restrict__ batch,
            int n) {
    int w = (blockIdx.x * 256 + threadIdx.x) >> 5;
    int lane = threadIdx.x & 31;
    if (w >= n) return;
    float acc = (lane < CDIM) ? __half2float(g_h10[w * H10P + lane]) : 0.f;
    int e0 = g_rowptr[w], e1 = g_rowptr[w + 1];
    for (int e = e0; e < e1; e += 32) {
        int me = e + lane;
        int ms = (me < e1) ? g_col[me] : NNODE;
        #pragma unroll
        for (int g = 0; g < 32; g += 8) {
            if (e + g >= e1) break;
            float v[8];
            #pragma unroll
            for (int j = 0; j < 8; j++) {
                int s = __shfl_sync(0xffffffffu, ms, g + j);
                v[j] = (lane < CDIM) ? __half2float(g_h10[s * H10P + lane]) : 0.f;
            }
            #pragma unroll
            for (int j = 0; j < 8; j++) acc += v[j];
        }
    }
    if (lane < CDIM) {
        float val = fmaf(g_dinv[w], acc, bias[lane]);
        int g = clampi(batch[w], NGRAPH);
        atomicAdd(&g_sums[g * CDIM + lane], val);
    }
}

__global__ void k_logsm(float* __restrict__ out) {
    int g = blockIdx.x * blockDim.x + threadIdx.x;
    if (g >= NGRAPH) return;
    float c = fmaxf(g_cnts[g], 1.0f);
    float p[CDIM];
    float m = -1e30f;
    #pragma unroll
    for (int i = 0; i < CDIM; i++) {
        p[i] = g_sums[g * CDIM + i] / c;
        m = fmaxf(m, p[i]);
    }
    float s = 0.f;
    #pragma unroll
    for (int i = 0; i < CDIM; i++) s += expf(p[i] - m);
    float l = logf(s);
    #pragma unroll
    for (int i = 0; i < CDIM; i++) out[g * CDIM + i] = p[i] - m - l;
}

// ---------------- launch -------------------------------------------------
extern "C" void kernel_launch(void* const* d_in, const int* in_sizes, int n_in,
                              void* d_out, int out_size) {
    const float* x     = (const float*)d_in[0];
    const int*   ei    = (const int*)d_in[1];
    const int*   batch = (const int*)d_in[2];
    const float* W_in  = (const float*)d_in[3];
    const float* b_in  = (const float*)d_in[4];
    const float* W_h0  = (const float*)d_in[5];
    const float* b_h0  = (const float*)d_in[6];
    const float* W_h1  = (const float*)d_in[7];
    const float* b_h1  = (const float*)d_in[8];
    const float* W_out = (const float*)d_in[9];
    const float* b_out = (const float*)d_in[10];

    int n = in_sizes[0] / HDIM;
    int E = in_sizes[1] / 2;

    // lazy one-time stream/event creation (first call is NOT captured)
    static cudaStream_t s1 = nullptr;
    static cudaEvent_t evFork = nullptr, evJoin = nullptr;
    if (s1 == nullptr) {
        cudaStreamCreateWithFlags(&s1, cudaStreamNonBlocking);
        cudaEventCreateWithFlags(&evFork, cudaEventDisableTiming);
        cudaEventCreateWithFlags(&evJoin, cudaEventDisableTiming);
    }

    const int TPB = 256;
    int nblk_e = (E + TPB - 1) / TPB;
    int nblk_n = (n + TPB - 1) / TPB;
    int nb = (n + 1023) / 1024;
    int gb = 2 * ((n + 127) / 128);
    int agg_blocks = (n * 32 + TPB - 1) / TPB;

    k_zero<<<nblk_n, TPB>>>(n);
    k_count<<<nblk_e, TPB>>>(ei, batch, E, n);
    k_dinv_prepW<<<nblk_n, TPB>>>(W_in, W_h0, W_h1, n);

    // fork: CSR build on s1, GEMM L1 on main stream
    cudaEventRecord(evFork, 0);
    cudaStreamWaitEvent(s1, evFork, 0);
    k_scan1<<<nb, 1024, 0, s1>>>(n);
    k_scan2<<<1, 128, 0, s1>>>(nb);
    k_scan3<<<nb, 1024, 0, s1>>>(n);
    k_fill<<<nblk_e, TPB, 0, s1>>>(ei, E, n);
    k_padfill<<<nblk_n, TPB, 0, s1>>>(n);
    cudaEventRecord(evJoin, s1);

    k_gemm_mma<<<gb, 256>>>(x, 0, n, 0);      // layer-1 GEMM overlaps CSR

    // join: aggregation needs both GEMM output and CSR
    cudaStreamWaitEvent(0, evJoin, 0);
    k_agg128<<<agg_blocks, TPB>>>(b_in, W_out, n, 0);
    // Layer 2
    k_gemm_mma<<<gb, 256>>>(x, 1, n, 1);
    k_agg128<<<agg_blocks, TPB>>>(b_h0, W_out, n, 0);
    // Layer 3 (+fused 128->10 projection, fp16 output)
    k_gemm_mma<<<gb, 256>>>(x, 2, n, 1);
    k_agg128<<<agg_blocks, TPB>>>(b_h1, W_out, n, 1);
    // Layer 4 aggregation fused with pooling
    k_agg10pool<<<agg_blocks, TPB>>>(b_out, batch, n);
    k_logsm<<<(NGRAPH + TPB - 1) / TPB, TPB>>>((float*)d_out);
}

// round 17
// speedup vs baseline: 1.1718x; 1.1718x over previous
#include <cuda_runtime.h>
#include <cuda_fp16.h>
#include <math.h>
#include <stdint.h>

#define NNODE  100000
#define EMAX   3200000
#define EPAD   4000064              // E + 8*N headroom (padded CSR)
#define HDIM   128
#define CDIM   10
#define H10P   16                   // padded h10 row (halves) = 32 B
#define NGRAPH 512

// ---------------- scratch (device globals; no allocation allowed) -------
__device__ __half g_hs16 [(NNODE + 1) * HDIM]; // +1 dummy zero row
__device__ __half g_feat16[NNODE * HDIM];
__device__ __half g_x16  [NNODE * HDIM];       // fp16 copy of input x
__device__ uint2  g_bfrag[3 * 8 * 16 * 32];    // W in mma B-fragment layout
__device__ __half g_h10 [(NNODE + 1) * H10P];  // fp16, sector-aligned rows
__device__ int   g_deg [NNODE];
__device__ float g_dinv[NNODE];
__device__ int   g_rowptr[NNODE + 1];
__device__ int   g_cursor[NNODE];
__device__ int   g_col [EPAD];
__device__ int   g_bsum[128];
__device__ int   g_boff[128];
__device__ float g_sums[NGRAPH * CDIM];
__device__ float g_cnts[NGRAPH];

__device__ __forceinline__ int clampi(int v, int n) {
    return (v < 0) ? 0 : ((v >= n) ? n - 1 : v);
}

__device__ __forceinline__ uint32_t smem_u32(const void* p) {
    uint32_t a;
    asm("{ .reg .u64 t; cvta.to.shared.u64 t, %1; cvt.u32.u64 %0, t; }"
        : "=r"(a) : "l"(p));
    return a;
}

// ---------------- init ---------------------------------------------------
__global__ void k_zero(int n) {
    int i = blockIdx.x * blockDim.x + threadIdx.x;
    if (i < n) g_deg[i] = 0;
    if (i < NGRAPH * CDIM) g_sums[i] = 0.0f;
    if (i < NGRAPH) g_cnts[i] = 0.0f;
    if (i < HDIM / 2) ((unsigned int*)(g_hs16 + NNODE * HDIM))[i] = 0u;
    if (i < H10P / 2) ((unsigned int*)(g_h10 + NNODE * H10P))[i] = 0u;
}

__global__ void k_count(const int* __restrict__ ei,
                        const int* __restrict__ batch, int E, int n) {
    int e = blockIdx.x * blockDim.x + threadIdx.x;
    if (e < E) atomicAdd(&g_deg[clampi(ei[E + e], n)], 1);
    if (e < n) atomicAdd(&g_cnts[clampi(batch[e], NGRAPH)], 1.0f);
}

// fused: dinv + W fragment packing
__global__ void k_dinv_prepW(const float* __restrict__ W0,
                             const float* __restrict__ W1,
                             const float* __restrict__ W2, int n) {
    int idx = blockIdx.x * blockDim.x + threadIdx.x;
    if (idx < n) g_dinv[idx] = rsqrtf((float)(g_deg[idx] + 1));
    if (idx < 3 * 8 * 16 * 32) {
        int lane = idx & 31;
        int f = (idx >> 5) & 15;
        int s = (idx >> 9) & 7;
        int l = idx >> 12;
        const float* W = (l == 0) ? W0 : (l == 1) ? W1 : W2;
        int kb = s * 16 + 2 * (lane & 3);
        int nn = f * 8 + (lane >> 2);
        __half2 h0 = __floats2half2_rn(W[kb * HDIM + nn], W[(kb + 1) * HDIM + nn]);
        __half2 h1 = __floats2half2_rn(W[(kb + 8) * HDIM + nn], W[(kb + 9) * HDIM + nn]);
        uint2 v;
        v.x = *(unsigned int*)&h0;
        v.y = *(unsigned int*)&h1;
        g_bfrag[idx] = v;
    }
}

// convert x (fp32) to fp16 once
__global__ void k_xcast(const float* __restrict__ x, int n) {
    int i = blockIdx.x * blockDim.x + threadIdx.x;   // one float4 per thread
    if (i >= n * (HDIM / 4)) return;
    float4 f = ((const float4*)x)[i];
    __half2 h0 = __floats2half2_rn(f.x, f.y);
    __half2 h1 = __floats2half2_rn(f.z, f.w);
    uint2 v;
    v.x = *(unsigned int*)&h0;
    v.y = *(unsigned int*)&h1;
    ((uint2*)g_x16)[i] = v;
}

// scans operate on PADDED degrees: pdeg = (deg+7) & ~7
__global__ void k_scan1(int n) {
    __shared__ int s[1024];
    int t = threadIdx.x;
    int i = blockIdx.x * 1024 + t;
    s[t] = (i < n) ? ((g_deg[i] + 7) & ~7) : 0;
    __syncthreads();
    for (int st = 512; st > 0; st >>= 1) {
        if (t < st) s[t] += s[t + st];
        __syncthreads();
    }
    if (t == 0) g_bsum[blockIdx.x] = s[0];
}

__global__ void k_scan2(int nb) {
    __shared__ int s[128];
    int t = threadIdx.x;
    int my = (t < nb) ? g_bsum[t] : 0;
    s[t] = my;
    __syncthreads();
    for (int st = 1; st < 128; st <<= 1) {
        int v = (t >= st) ? s[t - st] : 0;
        __syncthreads();
        s[t] += v;
        __syncthreads();
    }
    g_boff[t] = s[t] - my;
}

__global__ void k_scan3(int n) {
    __shared__ int s[1024];
    int t = threadIdx.x;
    int i = blockIdx.x * 1024 + t;
    int v0 = (i < n) ? ((g_deg[i] + 7) & ~7) : 0;
    s[t] = v0;
    __syncthreads();
    for (int st = 1; st < 1024; st <<= 1) {
        int v = (t >= st) ? s[t - st] : 0;
        __syncthreads();
        s[t] += v;
        __syncthreads();
    }
    if (i < n) {
        int excl = g_boff[blockIdx.x] + s[t] - v0;
        g_rowptr[i] = excl;
        g_cursor[i] = excl;
        if (i == n - 1) g_rowptr[n] = g_boff[blockIdx.x] + s[t];
    }
}

__global__ void k_fill(const int* __restrict__ ei, int E, int n) {
    int e = blockIdx.x * blockDim.x + threadIdx.x;
    if (e < E) {
        int src = clampi(ei[e], n);
        int dst = clampi(ei[E + e], n);
        int p = atomicAdd(&g_cursor[dst], 1);
        g_col[p] = src;
    }
}

// fill padding slots (<=7 per node) with dummy index
__global__ void k_padfill(int n) {
    int i = blockIdx.x * blockDim.x + threadIdx.x;
    if (i >= n) return;
    int p0 = g_rowptr[i] + g_deg[i];
    int p1 = g_rowptr[i + 1];
    for (int p = p0; p < p1; p++) g_col[p] = NNODE;
}

// ---------------- HMMA GEMM (8-warp smem/ldmatrix, N-split) --------------
// src: 0 -> g_x16, 1 -> g_feat16 (both fp16 row-major)
#define APAD 136
__global__ void __launch_bounds__(256)
k_gemm_mma(int layer, int n, int src) {
    __shared__ __half As[128 * APAD];
    int tid = threadIdx.x;
    int wid = tid >> 5, lane = tid & 31;
    int nh = blockIdx.x & 1;
    int rb = (blockIdx.x >> 1) * 128;
    const __half* X = src ? g_feat16 : g_x16;

    for (int i = tid; i < 2048; i += 256) {
        int r = i >> 4, j = i & 15;
        int gr = rb + r;
        uint4 v = make_uint4(0u, 0u, 0u, 0u);
        if (gr < n) v = *(const uint4*)(X + (long long)gr * HDIM + j * 8);
        *(uint4*)&As[r * APAD + j * 8] = v;
    }
    __syncthreads();

    float acc[8][4];
    #pragma unroll
    for (int f = 0; f < 8; f++)
        #pragma unroll
        for (int j = 0; j < 4; j++) acc[f][j] = 0.f;

    const uint2* bf = g_bfrag + (layer * 8) * 16 * 32 + (nh * 8) * 32;
    int wr = wid * 16;
    int g = lane >> 3, rr = lane & 7;
    uint32_t a_base = smem_u32(As) +
        (uint32_t)(((wr + (g & 1) * 8 + rr) * APAD) * 2);

    #pragma unroll
    for (int s = 0; s < 8; s++) {
        uint32_t a0, a1, a2, a3;
        uint32_t addr = a_base + (uint32_t)((s * 16 + (g >> 1) * 8) * 2);
        asm volatile("ldmatrix.sync.aligned.m8n8.x4.shared.b16 {%0,%1,%2,%3}, [%4];"
                     : "=r"(a0), "=r"(a1), "=r"(a2), "=r"(a3) : "r"(addr));
        const uint2* bs = bf + s * 16 * 32 + lane;
        #pragma unroll
        for (int f = 0; f < 8; f++) {
            uint2 b = __ldg(&bs[f * 32]);
            asm volatile(
                "mma.sync.aligned.m16n8k16.row.col.f32.f16.f16.f32 "
                "{%0,%1,%2,%3}, {%4,%5,%6,%7}, {%8,%9}, {%0,%1,%2,%3};"
                : "+f"(acc[f][0]), "+f"(acc[f][1]), "+f"(acc[f][2]), "+f"(acc[f][3])
                : "r"(a0), "r"(a1), "r"(a2), "r"(a3), "r"(b.x), "r"(b.y));
        }
    }

    int r0 = rb + wr + (lane >> 2);
    int r1 = r0 + 8;
    float di0 = (r0 < n) ? g_dinv[r0] : 0.f;
    float di1 = (r1 < n) ? g_dinv[r1] : 0.f;
    #pragma unroll
    for (int f = 0; f < 8; f++) {
        int c = nh * 64 + f * 8 + 2 * (lane & 3);
        if (r0 < n) {
            __half2 h = __floats2half2_rn(acc[f][0] * di0, acc[f][1] * di0);
            *(unsigned int*)(g_hs16 + (long long)r0 * HDIM + c) = *(unsigned int*)&h;
        }
        if (r1 < n) {
            __half2 h = __floats2half2_rn(acc[f][2] * di1, acc[f][3] * di1);
            *(unsigned int*)(g_hs16 + (long long)r1 * HDIM + c) = *(unsigned int*)&h;
        }
    }
}

// ---------------- 128-wide pull aggregation (R13 proven form) ------------
__global__ void __launch_bounds__(256)
k_agg128(const float* __restrict__ bias, const float* __restrict__ Wout,
         int n, int fin) {
    __shared__ float Wsm[HDIM * CDIM];
    if (fin) {
        for (int i = threadIdx.x; i < HDIM * CDIM; i += 256)
            Wsm[i] = Wout[i];
        __syncthreads();
    }
    int w = (blockIdx.x * 256 + threadIdx.x) >> 5;
    int lane = threadIdx.x & 31;
    if (w >= n) return;
    const uint2* base = (const uint2*)g_hs16;
    float4 acc;
    {
        uint2 v = base[w * 32 + lane];       // self loop
        float2 f0 = __half22float2(*(__half2*)&v.x);
        float2 f1 = __half22float2(*(__half2*)&v.y);
        acc.x = f0.x; acc.y = f0.y; acc.z = f1.x; acc.w = f1.y;
    }
    int e0 = g_rowptr[w], e1 = g_rowptr[w + 1];
    for (int e = e0; e < e1; e += 32) {
        int me = e + lane;
        int ms = (me < e1) ? g_col[me] : NNODE;
        #pragma unroll
        for (int g = 0; g < 32; g += 8) {
            if (e + g >= e1) break;          // groups of 8 always complete
            uint2 b[8];
            #pragma unroll
            for (int j = 0; j < 8; j++) {
                int s = __shfl_sync(0xffffffffu, ms, g + j);
                b[j] = base[s * 32 + lane];
            }
            #pragma unroll
            for (int j = 0; j < 8; j++) {
                float2 f0 = __half22float2(*(__half2*)&b[j].x);
                float2 f1 = __half22float2(*(__half2*)&b[j].y);
                acc.x += f0.x; acc.y += f0.y; acc.z += f1.x; acc.w += f1.y;
            }
        }
    }
    float di = g_dinv[w];
    float4 bv = ((const float4*)bias)[lane];
    float4 o;
    o.x = fmaxf(fmaf(di, acc.x, bv.x), 0.f);
    o.y = fmaxf(fmaf(di, acc.y, bv.y), 0.f);
    o.z = fmaxf(fmaf(di, acc.z, bv.z), 0.f);
    o.w = fmaxf(fmaf(di, acc.w, bv.w), 0.f);

    if (!fin) {
        __half2 h0 = __floats2half2_rn(o.x, o.y);
        __half2 h1 = __floats2half2_rn(o.z, o.w);
        uint2 st;
        st.x = *(unsigned int*)&h0;
        st.y = *(unsigned int*)&h1;
        ((uint2*)g_feat16)[w * 32 + lane] = st;
    } else {
        float oa[4] = {o.x, o.y, o.z, o.w};
        float p[CDIM];
        #pragma unroll
        for (int c = 0; c < CDIM; c++) p[c] = 0.f;
        #pragma unroll
        for (int j = 0; j < 4; j++) {
            const float* wr = &Wsm[(4 * lane + j) * CDIM];
            #pragma unroll
            for (int c = 0; c < CDIM; c++)
                p[c] = fmaf(oa[j], wr[c], p[c]);
        }
        #pragma unroll
        for (int c = 0; c < CDIM; c++) {
            #pragma unroll
            for (int off = 16; off > 0; off >>= 1)
                p[c] += __shfl_xor_sync(0xffffffffu, p[c], off);
        }
        if (lane == 0) {
            __half* dst = &g_h10[w * H10P];
            unsigned int pk[8];
            #pragma unroll
            for (int c = 0; c < 5; c++) {
                __half2 h = __floats2half2_rn(p[2 * c] * di, p[2 * c + 1] * di);
                pk[c] = *(unsigned int*)&h;
            }
            pk[5] = 0u; pk[6] = 0u; pk[7] = 0u;
            uint4* d4 = (uint4*)dst;
            d4[0] = make_uint4(pk[0], pk[1], pk[2], pk[3]);
            d4[1] = make_uint4(pk[4], pk[5], pk[6], pk[7]);
        }
    }
}

// 10-wide aggregation fused with mean-pool (fp16 h10, padded CSR)
__global__ void __launch_bounds__(256)
k_agg10pool(const float* __restrict__ bias, const int* __restrict__ batch,
            int n) {
    int w = (blockIdx.x * 256 + threadIdx.x) >> 5;
    int lane = threadIdx.x & 31;
    if (w >= n) return;
    float acc = (lane < CDIM) ? __half2float(g_h10[w * H10P + lane]) : 0.f;
    int e0 = g_rowptr[w], e1 = g_rowptr[w + 1];
    for (int e = e0; e < e1; e += 32) {
        int me = e + lane;
        int ms = (me < e1) ? g_col[me] : NNODE;
        #pragma unroll
        for (int g = 0; g < 32; g += 8) {
            if (e + g >= e1) break;
            float v[8];
            #pragma unroll
            for (int j = 0; j < 8; j++) {
                int s = __shfl_sync(0xffffffffu, ms, g + j);
                v[j] = (lane < CDIM) ? __half2float(g_h10[s * H10P + lane]) : 0.f;
            }
            #pragma unroll
            for (int j = 0; j < 8; j++) acc += v[j];
        }
    }
    if (lane < CDIM) {
        float val = fmaf(g_dinv[w], acc, bias[lane]);
        int g = clampi(batch[w], NGRAPH);
        atomicAdd(&g_sums[g * CDIM + lane], val);
    }
}

__global__ void k_logsm(float* __restrict__ out) {
    int g = blockIdx.x * blockDim.x + threadIdx.x;
    if (g >= NGRAPH) return;
    float c = fmaxf(g_cnts[g], 1.0f);
    float p[CDIM];
    float m = -1e30f;
    #pragma unroll
    for (int i = 0; i < CDIM; i++) {
        p[i] = g_sums[g * CDIM + i] / c;
        m = fmaxf(m, p[i]);
    }
    float s = 0.f;
    #pragma unroll
    for (int i = 0; i < CDIM; i++) s += expf(p[i] - m);
    float l = logf(s);
    #pragma unroll
    for (int i = 0; i < CDIM; i++) out[g * CDIM + i] = p[i] - m - l;
}

// ---------------- launch -------------------------------------------------
extern "C" void kernel_launch(void* const* d_in, const int* in_sizes, int n_in,
                              void* d_out, int out_size) {
    const float* x     = (const float*)d_in[0];
    const int*   ei    = (const int*)d_in[1];
    const int*   batch = (const int*)d_in[2];
    const float* W_in  = (const float*)d_in[3];
    const float* b_in  = (const float*)d_in[4];
    const float* W_h0  = (const float*)d_in[5];
    const float* b_h0  = (const float*)d_in[6];
    const float* W_h1  = (const float*)d_in[7];
    const float* b_h1  = (const float*)d_in[8];
    const float* W_out = (const float*)d_in[9];
    const float* b_out = (const float*)d_in[10];

    int n = in_sizes[0] / HDIM;
    int E = in_sizes[1] / 2;

    // lazy one-time stream/event creation (first call is NOT captured)
    static cudaStream_t s1 = nullptr;
    static cudaEvent_t evFork = nullptr, evJoin = nullptr;
    if (s1 == nullptr) {
        cudaStreamCreateWithFlags(&s1, cudaStreamNonBlocking);
        cudaEventCreateWithFlags(&evFork, cudaEventDisableTiming);
        cudaEventCreateWithFlags(&evJoin, cudaEventDisableTiming);
    }

    const int TPB = 256;
    int nblk_e = (E + TPB - 1) / TPB;
    int nblk_n = (n + TPB - 1) / TPB;
    int nb = (n + 1023) / 1024;
    int gb = 2 * ((n + 127) / 128);
    int agg_blocks = (n * 32 + TPB - 1) / TPB;
    int xc_blocks = (n * (HDIM / 4) + TPB - 1) / TPB;

    k_zero<<<nblk_n, TPB>>>(n);
    k_count<<<nblk_e, TPB>>>(ei, batch, E, n);
    k_dinv_prepW<<<nblk_n, TPB>>>(W_in, W_h0, W_h1, n);

    // fork: CSR build on s1; xcast + GEMM L1 on main stream
    cudaEventRecord(evFork, 0);
    cudaStreamWaitEvent(s1, evFork, 0);
    k_scan1<<<nb, 1024, 0, s1>>>(n);
    k_scan2<<<1, 128, 0, s1>>>(nb);
    k_scan3<<<nb, 1024, 0, s1>>>(n);
    k_fill<<<nblk_e, TPB, 0, s1>>>(ei, E, n);
    k_padfill<<<nblk_n, TPB, 0, s1>>>(n);
    cudaEventRecord(evJoin, s1);

    k_xcast<<<xc_blocks, TPB>>>(x, n);
    k_gemm_mma<<<gb, 256>>>(0, n, 0);         // layer-1 GEMM (fp16 input)

    // join: aggregation needs both GEMM output and CSR
    cudaStreamWaitEvent(0, evJoin, 0);
    k_agg128<<<agg_blocks, TPB>>>(b_in, W_out, n, 0);
    // Layer 2
    k_gemm_mma<<<gb, 256>>>(1, n, 1);
    k_agg128<<<agg_blocks, TPB>>>(b_h0, W_out, n, 0);
    // Layer 3 (+fused 128->10 projection, fp16 output)
    k_gemm_mma<<<gb, 256>>>(2, n, 1);
    k_agg128<<<agg_blocks, TPB>>>(b_h1, W_out, n, 1);
    // Layer 4 aggregation fused with pooling
    k_agg10pool<<<agg_blocks, TPB>>>(b_out, batch, n);
    k_logsm<<<(NGRAPH + TPB - 1) / TPB, TPB>>>((float*)d_out);
}